// round 17
// baseline (speedup 1.0000x reference)
#include <cuda_runtime.h>
#include <cuda_fp16.h>
#include <cstdint>

#define NN 60000
#define EE 600000
#define DD 128
#define SLOPE 0.01f
#define BB 256            // build blocks (co-resident @ 2/SM)
#define BT 1024           // build threads
#define NBLK 7500         // agg stats partial blocks (60000/8)
#define GEMM_GRID 296     // persistent GEMM: 2 CTAs/SM

typedef unsigned long long ull;

// ---------------- device scratch (static, no allocation) ----------------
__device__ int   g_is64;
__device__ int   g_cnt[NN];
__device__ int   g_part[BB];
__device__ int   g_rowstart[NN + 1];
__device__ int   g_next[NN];
__device__ int2  g_edge[EE];
__device__ float g_dinv[NN];
__device__ __half g_ah[(size_t)NN * DD];    // pre-transformed GEMM input (fp16)
__device__ __half g_xwh[(size_t)NN * DD];   // GEMM output (fp16, gather side)
__device__ float g_h[(size_t)NN * DD];      // agg output, fp32
__device__ float g_psum[(size_t)NBLK * DD];
__device__ float g_psq[(size_t)NBLK * DD];
__device__ float g_scale[DD];
__device__ float g_shift[DD];
__device__ unsigned g_barcnt;
__device__ unsigned g_epoch;
// W as fp16, row-major [k][n]: [layer][128*128]
__device__ __align__(16) __half g_wh[3][16384];

// ---------------- mma.sync / ldmatrix / cp.async primitives ----------------
__device__ __forceinline__ uint32_t smem_u32(const void* p) {
    return (uint32_t)__cvta_generic_to_shared(p);
}
#define LDSM4(r, addr)                                                         \
    asm volatile("ldmatrix.sync.aligned.m8n8.x4.shared.b16 {%0,%1,%2,%3}, [%4];" \
                 : "=r"((r)[0]), "=r"((r)[1]), "=r"((r)[2]), "=r"((r)[3])      \
                 : "r"(addr))
#define LDSM4T(r, addr)                                                        \
    asm volatile("ldmatrix.sync.aligned.m8n8.x4.trans.shared.b16 {%0,%1,%2,%3}, [%4];" \
                 : "=r"((r)[0]), "=r"((r)[1]), "=r"((r)[2]), "=r"((r)[3])      \
                 : "r"(addr))
#define MMA16816H(d, a, b0, b1)                                                \
    asm volatile("mma.sync.aligned.m16n8k16.row.col.f32.f16.f16.f32 "          \
                 "{%0,%1,%2,%3},{%4,%5,%6,%7},{%8,%9},{%0,%1,%2,%3};"          \
                 : "+f"((d)[0]), "+f"((d)[1]), "+f"((d)[2]), "+f"((d)[3])      \
                 : "r"((a)[0]), "r"((a)[1]), "r"((a)[2]), "r"((a)[3]),         \
                   "r"(b0), "r"(b1))
#define CP16(dst, src)                                                         \
    asm volatile("cp.async.ca.shared.global [%0], [%1], 16;"                   \
                 :: "r"(dst), "l"(src))
#define CP_COMMIT() asm volatile("cp.async.commit_group;" ::: "memory")
#define CP_WAIT0()  asm volatile("cp.async.wait_group 0;" ::: "memory")
#define CP_WAIT1()  asm volatile("cp.async.wait_group 1;" ::: "memory")

// ---------------- global spin barrier (BB blocks resident) -----------------
__device__ __forceinline__ void gsync() {
    __syncthreads();
    if (threadIdx.x == 0) {
        __threadfence();
        unsigned e = atomicAdd(&g_epoch, 0u);
        if (atomicAdd(&g_barcnt, 1u) == BB - 1u) {
            g_barcnt = 0u;
            __threadfence();
            atomicAdd(&g_epoch, 1u);
        } else {
            while (((volatile unsigned*)&g_epoch)[0] == e) { __nanosleep(64); }
        }
        __threadfence();
    }
    __syncthreads();
}

__device__ __forceinline__ int edge_at(const void* p, int idx, int is64) {
    return is64 ? ((const int*)p)[2 * idx] : ((const int*)p)[idx];
}

// ---------------- fused CSR build (1024 threads x 256 blocks, 2/SM) --------
__global__ __launch_bounds__(BT, 2) void k_build(const void* ei) {
    int t = threadIdx.x, b = blockIdx.x;
    int gid = b * BT + t;
    const int GSTR = BB * BT;

    if (gid == 0) {
        const long long* q = (const long long*)ei;
        int ok = 1;
        for (int j = 0; j < 256; j++) {
            long long v = q[j];
            if (v < 0 || v >= NN) { ok = 0; break; }
        }
        g_is64 = ok;
    }
    for (int i = gid; i < NN; i += GSTR) g_cnt[i] = 0;
    gsync();
    int is64 = g_is64;

    for (int e = gid; e < EE; e += GSTR) {
        int d = edge_at(ei, EE + e, is64);
        atomicAdd(&g_cnt[d], 1);
    }
    gsync();

    __shared__ int s[BT];
    __shared__ int sp[BB];
    int i = gid;
    int x = (i < NN) ? g_cnt[i] : 0;
    if (i < NN) g_dinv[i] = rsqrtf((float)(x + 1));
    s[t] = x;
    __syncthreads();
    for (int off = 1; off < BT; off <<= 1) {
        int v = (t >= off) ? s[t - off] : 0;
        __syncthreads();
        s[t] += v;
        __syncthreads();
    }
    int incl = s[t];
    if (t == BT - 1) g_part[b] = incl;
    gsync();

    if (t < BB) sp[t] = g_part[t];
    __syncthreads();
    for (int off = 1; off < BB; off <<= 1) {
        int v = 0;
        if (t < BB && t >= off) v = sp[t - off];
        __syncthreads();
        if (t < BB) sp[t] += v;
        __syncthreads();
    }
    int pre = (b > 0) ? sp[b - 1] : 0;
    if (i < NN) {
        int rs = pre + incl - x;
        g_rowstart[i] = rs;
        g_next[i] = rs;
    }
    if (gid == 0) g_rowstart[NN] = EE;
    gsync();

    for (int e = gid; e < EE; e += GSTR) {
        int sdx = edge_at(ei, e, is64);
        int dd  = edge_at(ei, EE + e, is64);
        int pos = atomicAdd(&g_next[dd], 1);
        g_edge[pos] = make_int2(sdx, __float_as_int(g_dinv[sdx]));
    }
}

// ---------------- W convert to fp16 (once per call) ----------------
__global__ void k_wconv(const float* __restrict__ w0, const float* __restrict__ w1,
                        const float* __restrict__ w2) {
    const float* W = (blockIdx.x == 0) ? w0 : ((blockIdx.x == 1) ? w1 : w2);
    __half* d1 = g_wh[blockIdx.x];
    for (int idx = threadIdx.x; idx < 16384; idx += 256) {
        d1[idx] = __float2half(W[idx]);
    }
}

// ---------- prep: BN + LeakyReLU (optional) + fp32 -> fp16 -----------------
__global__ __launch_bounds__(256) void k_prep(
    const float* __restrict__ in, __half* __restrict__ outp, int use_bn, int act)
{
    int idx = blockIdx.x * blockDim.x + threadIdx.x;   // float4 index
    if (idx < NN * DD / 4) {
        float4 v = *(const float4*)(in + (size_t)idx * 4);
        int d = (idx & 31) * 4;
        if (use_bn) {
            v.x = v.x * g_scale[d + 0] + g_shift[d + 0];
            v.y = v.y * g_scale[d + 1] + g_shift[d + 1];
            v.z = v.z * g_scale[d + 2] + g_shift[d + 2];
            v.w = v.w * g_scale[d + 3] + g_shift[d + 3];
            if (act) {
                v.x = v.x >= 0.f ? v.x : SLOPE * v.x;
                v.y = v.y >= 0.f ? v.y : SLOPE * v.y;
                v.z = v.z >= 0.f ? v.z : SLOPE * v.z;
                v.w = v.w >= 0.f ? v.w : SLOPE * v.w;
            }
        }
        __half2 h0 = __floats2half2_rn(v.x, v.y);
        __half2 h1 = __floats2half2_rn(v.z, v.w);
        uint2 u;
        u.x = *(uint32_t*)&h0; u.y = *(uint32_t*)&h1;
        *(uint2*)(outp + (size_t)idx * 4) = u;
    }
}

// ---- persistent pure-fp16 GEMM: cp.async double-buffered A, W in regs -----
// grid=296 (2 CTAs/SM), 256 threads = 8 warps (1m x 8n), warp tile 64x16.
// smem: W stage 32KB at prologue, then two 16KB A tile buffers.
__global__ __launch_bounds__(256, 2) void k_gemm_p(
    const __half* __restrict__ Ah, int layer, __half* __restrict__ C)
{
    __shared__ unsigned char smb[32768];
    uint32_t sb = smem_u32(smb);

    int t = threadIdx.x, lane = t & 31, wid = t >> 5;
    int no = wid * 16;                     // warp col strip
    const int GT = (NN + 63) / 64;         // 938 tiles

    int lr = (lane & 7) + (lane & 8);
    int lc = (lane >> 4) & 1;

    // prologue: stage W swizzled, load frags to regs
    {
        const uint4* s1 = (const uint4*)g_wh[layer];
        for (int i = t; i < 2048; i += 256) {
            int row = i >> 4, g = i & 15;
            uint32_t off = (uint32_t)row * 256u + (uint32_t)((g ^ (row & 7)) << 4);
            *(uint4*)(smb + off) = s1[i];
        }
    }
    __syncthreads();
    uint32_t breg[8][4];
#pragma unroll
    for (int ks = 0; ks < 8; ks++) {
        uint32_t brow = (uint32_t)(ks * 16 + lr);
        uint32_t bg = (uint32_t)((no >> 3) + lc);
        uint32_t boff = brow * 256u + ((bg ^ (brow & 7u)) << 4);
        LDSM4T(breg[ks], sb + boff);
    }
    __syncthreads();   // frags in regs; smem becomes A double buffer

    // stage A tile tl (64x128 fp16 = 16KB) into buffer p via cp.async
#define STAGE(tl, p)                                                           \
    {                                                                          \
        int _r0 = (tl) * 64;                                                   \
        uint32_t _base = sb + (p) * 16384u;                                    \
        _Pragma("unroll")                                                      \
        for (int j = 0; j < 4; j++) {                                          \
            int gi = t + j * 256;                                              \
            int row = gi >> 4, g = gi & 15;                                    \
            int gr = _r0 + row;                                                \
            uint32_t dst = _base + (uint32_t)row * 256u                        \
                         + (uint32_t)((g ^ (row & 7)) << 4);                   \
            if (gr < NN) {                                                     \
                CP16(dst, (const void*)(Ah + (size_t)gr * DD + g * 8));        \
            } else {                                                           \
                *(uint4*)(smb + (p) * 16384u + (uint32_t)row * 256u            \
                          + (uint32_t)((g ^ (row & 7)) << 4)) =                \
                    make_uint4(0u, 0u, 0u, 0u);                                \
            }                                                                  \
        }                                                                      \
        CP_COMMIT();                                                           \
    }

    int tile = blockIdx.x;
    if (tile < GT) STAGE(tile, 0);

    int p = 0;
    for (; tile < GT; tile += gridDim.x) {
        int next = tile + gridDim.x;
        bool has_next = next < GT;
        if (has_next) STAGE(next, p ^ 1);

        if (has_next) { CP_WAIT1(); } else { CP_WAIT0(); }
        __syncthreads();   // buffer p complete for all warps

        uint32_t ab = sb + p * 16384u;
        float acc[4][2][4];
#pragma unroll
        for (int m = 0; m < 4; m++)
#pragma unroll
            for (int n = 0; n < 2; n++)
#pragma unroll
                for (int q = 0; q < 4; q++) acc[m][n][q] = 0.f;

#pragma unroll
        for (int ks = 0; ks < 8; ks++) {
            uint32_t ar[4][4];
#pragma unroll
            for (int m = 0; m < 4; m++) {
                uint32_t arow = (uint32_t)(m * 16 + lr);
                uint32_t ag = (uint32_t)(ks * 2 + lc);
                uint32_t aoff = arow * 256u + ((ag ^ (arow & 7u)) << 4);
                LDSM4(ar[m], ab + aoff);
            }
#pragma unroll
            for (int m = 0; m < 4; m++) {
                MMA16816H(acc[m][0], ar[m], breg[ks][0], breg[ks][1]);
                MMA16816H(acc[m][1], ar[m], breg[ks][2], breg[ks][3]);
            }
        }

        // epilogue: fp16 stores (m16n8 lane mapping), NN % 16 == 0
        int r0 = tile * 64;
#pragma unroll
        for (int m = 0; m < 4; m++) {
            int rbm = r0 + m * 16;
            if (rbm + 16 <= NN) {
                int rr = rbm + (lane >> 2);
                int cc = no + (lane & 3) * 2;
#pragma unroll
                for (int n = 0; n < 2; n++) {
                    __half2 h0 = __floats2half2_rn(acc[m][n][0], acc[m][n][1]);
                    __half2 h1 = __floats2half2_rn(acc[m][n][2], acc[m][n][3]);
                    *(__half2*)(C + (size_t)rr * DD + cc + n * 8) = h0;
                    *(__half2*)(C + (size_t)(rr + 8) * DD + cc + n * 8) = h1;
                }
            }
        }
        __syncthreads();   // all warps done reading buf p before it's restaged
        p ^= 1;
    }
#undef STAGE
}

// ---- aggregation: warp/node CSR gather of fp16 rows + fused BN stats ------
__device__ __forceinline__ void acc4(float4& a, float c, uint2 u) {
    float2 f0 = __half22float2(*(__half2*)&u.x);
    float2 f1 = __half22float2(*(__half2*)&u.y);
    a.x = fmaf(c, f0.x, a.x); a.y = fmaf(c, f0.y, a.y);
    a.z = fmaf(c, f1.x, a.z); a.w = fmaf(c, f1.y, a.w);
}

__global__ __launch_bounds__(256, 7) void k_agg(
    const __half* __restrict__ xw, float* __restrict__ outp,
    float* __restrict__ psum, float* __restrict__ psq)
{
    __shared__ float s1[8][128], s2[8][128];
    int t = threadIdx.x;
    int wid = t >> 5, lane = t & 31;
    int w = blockIdx.x * 8 + wid;
    float di = g_dinv[w];

    uint2 us = __ldg((const uint2*)(xw + (size_t)w * DD) + lane);
    float4 acc = make_float4(0.f, 0.f, 0.f, 0.f);
    acc4(acc, di * di, us);

    int beg = g_rowstart[w], end = g_rowstart[w + 1];
    int i = beg;
    for (; i + 3 < end; i += 4) {
        int2 e0 = __ldg(&g_edge[i + 0]);
        int2 e1 = __ldg(&g_edge[i + 1]);
        int2 e2 = __ldg(&g_edge[i + 2]);
        int2 e3 = __ldg(&g_edge[i + 3]);
        uint2 v0 = __ldg((const uint2*)(xw + (size_t)e0.x * DD) + lane);
        uint2 v1 = __ldg((const uint2*)(xw + (size_t)e1.x * DD) + lane);
        uint2 v2 = __ldg((const uint2*)(xw + (size_t)e2.x * DD) + lane);
        uint2 v3 = __ldg((const uint2*)(xw + (size_t)e3.x * DD) + lane);
        acc4(acc, di * __int_as_float(e0.y), v0);
        acc4(acc, di * __int_as_float(e1.y), v1);
        acc4(acc, di * __int_as_float(e2.y), v2);
        acc4(acc, di * __int_as_float(e3.y), v3);
    }
    if (i < end) {
        int last = end - 1;
        int2 e0 = __ldg(&g_edge[i]);
        int2 e1 = __ldg(&g_edge[min(i + 1, last)]);
        int2 e2 = __ldg(&g_edge[min(i + 2, last)]);
        uint2 v0 = __ldg((const uint2*)(xw + (size_t)e0.x * DD) + lane);
        uint2 v1 = __ldg((const uint2*)(xw + (size_t)e1.x * DD) + lane);
        uint2 v2 = __ldg((const uint2*)(xw + (size_t)e2.x * DD) + lane);
        float c1 = (i + 1 < end) ? di * __int_as_float(e1.y) : 0.f;
        float c2 = (i + 2 < end) ? di * __int_as_float(e2.y) : 0.f;
        acc4(acc, di * __int_as_float(e0.y), v0);
        acc4(acc, c1, v1);
        acc4(acc, c2, v2);
    }
    reinterpret_cast<float4*>(outp + (size_t)w * DD)[lane] = acc;

    reinterpret_cast<float4*>(&s1[wid][0])[lane] = acc;
    reinterpret_cast<float4*>(&s2[wid][0])[lane] =
        make_float4(acc.x * acc.x, acc.y * acc.y, acc.z * acc.z, acc.w * acc.w);
    __syncthreads();
    if (t < 128) {
        float a = 0.f, b = 0.f;
#pragma unroll
        for (int ww = 0; ww < 8; ww++) { a += s1[ww][t]; b += s2[ww][t]; }
        psum[(size_t)blockIdx.x * DD + t] = a;
        psq [(size_t)blockIdx.x * DD + t] = b;
    }
}

// ---------------- BN stats finalize: block per feature ----------------
__global__ __launch_bounds__(256) void k_stats2(
    const float* __restrict__ gw, const float* __restrict__ be)
{
    __shared__ double r1[256], r2[256];
    int d = blockIdx.x;
    double s = 0.0, q = 0.0;
    for (int b = threadIdx.x; b < NBLK; b += 256) {
        s += (double)g_psum[(size_t)b * DD + d];
        q += (double)g_psq [(size_t)b * DD + d];
    }
    r1[threadIdx.x] = s; r2[threadIdx.x] = q;
    __syncthreads();
    for (int off = 128; off > 0; off >>= 1) {
        if (threadIdx.x < off) {
            r1[threadIdx.x] += r1[threadIdx.x + off];
            r2[threadIdx.x] += r2[threadIdx.x + off];
        }
        __syncthreads();
    }
    if (threadIdx.x == 0) {
        double mu = r1[0] / (double)NN;
        double var = r2[0] / (double)NN - mu * mu;
        float inv = (float)(1.0 / sqrt(var + 1e-5));
        float scl = gw[d] * inv;
        g_scale[d] = scl;
        g_shift[d] = be[d] - (float)mu * scl;
    }
}

// ---------------- final BN apply (fp32 in-place) ----------------
__global__ void k_apply(float* __restrict__ h) {
    int idx = blockIdx.x * blockDim.x + threadIdx.x;
    if (idx < NN * DD / 4) {
        float4 v = reinterpret_cast<float4*>(h)[idx];
        int d = (idx & 31) * 4;
        v.x = v.x * g_scale[d + 0] + g_shift[d + 0];
        v.y = v.y * g_scale[d + 1] + g_shift[d + 1];
        v.z = v.z * g_scale[d + 2] + g_shift[d + 2];
        v.w = v.w * g_scale[d + 3] + g_shift[d + 3];
        reinterpret_cast<float4*>(h)[idx] = v;
    }
}

// ---------------- host launcher ----------------
extern "C" void kernel_launch(void* const* d_in, const int* in_sizes, int n_in,
                              void* d_out, int out_size) {
    const float* x   = (const float*)d_in[0];
    const void*  ei  = d_in[1];
    const float* w0  = (const float*)d_in[2];
    const float* g0  = (const float*)d_in[4];
    const float* be0 = (const float*)d_in[5];
    const float* w1  = (const float*)d_in[6];
    const float* g1  = (const float*)d_in[8];
    const float* be1 = (const float*)d_in[9];
    const float* w2  = (const float*)d_in[10];
    const float* g2  = (const float*)d_in[12];
    const float* be2 = (const float*)d_in[13];
    float* out = (float*)d_out;

    __half *ah, *xwh;
    float *h, *ps, *pq;
    cudaGetSymbolAddress((void**)&ah,  g_ah);
    cudaGetSymbolAddress((void**)&xwh, g_xwh);
    cudaGetSymbolAddress((void**)&h,   g_h);
    cudaGetSymbolAddress((void**)&ps,  g_psum);
    cudaGetSymbolAddress((void**)&pq,  g_psq);

    const int TB = 256;
    const int gbP = NN * DD / 4 / TB;   // 7500

    // layer 0 (launch #4 = pure-fp16 cp.async GEMM -> ncu capture slot)
    k_build<<<BB, BT>>>(ei);                               // 1
    k_wconv<<<3, TB>>>(w0, w1, w2);                        // 2
    k_prep<<<gbP, TB>>>(x, ah, 0, 0);                      // 3
    k_gemm_p<<<GEMM_GRID, TB>>>(ah, 0, xwh);               // 4 <- profiled
    k_agg<<<NBLK, TB>>>(xwh, h, ps, pq);                   // 5
    k_stats2<<<DD, TB>>>(g0, be0);                         // 6

    // layer 1 (BN0 + LeakyReLU applied in prep)
    k_prep<<<gbP, TB>>>(h, ah, 1, 1);
    k_gemm_p<<<GEMM_GRID, TB>>>(ah, 1, xwh);
    k_agg<<<NBLK, TB>>>(xwh, h, ps, pq);
    k_stats2<<<DD, TB>>>(g1, be1);

    // layer 2 (BN1 + LeakyReLU applied in prep), final BN standalone
    k_prep<<<gbP, TB>>>(h, ah, 1, 1);
    k_gemm_p<<<GEMM_GRID, TB>>>(ah, 2, xwh);
    k_agg<<<NBLK, TB>>>(xwh, out, ps, pq);
    k_stats2<<<DD, TB>>>(g2, be2);
    k_apply<<<gbP, TB>>>(out);
}